// round 16
// baseline (speedup 1.0000x reference)
#include <cuda_runtime.h>
#include <cuda_bf16.h>
#include <cstdint>

// Problem constants
#define BATCH 8192
#define FEAT  512
#define DEG   32
#define F2    1024   // 2*FEAT
#define F3    1536   // 3*FEAT
#define BN_EPS 1e-5f

// Output layout (floats): agg, to_feats, gen, raw, env_gen, env_raw
#define OFF_AGG   0
#define OFF_TO    (BATCH*FEAT)
#define OFF_GEN   (OFF_TO   + BATCH*F3)
#define OFF_RAW   (OFF_GEN  + BATCH*F2)
#define OFF_EGEN  (OFF_RAW  + BATCH*F2)
#define OFF_ERAW  (OFF_EGEN + BATCH*F2)

// ---------------- scratch (__device__ globals; no allocations) --------------
__device__ float g_cat [(size_t)BATCH * F2];   // [self | agg] tf32-rounded
__device__ float g_env [(size_t)BATCH * FEAT]; // env_agg tf32-rounded
__device__ float g_genr[(size_t)BATCH * F2];   // tf32-rounded relu(raw) = gen
__device__ float g_WgT [(size_t)F2 * F2];      // W_gen^T rounded, [N][K] K-major
__device__ float g_W1T [(size_t)F3 * F3];      // W1^T exact, [N][K]
__device__ float g_W1sT[(size_t)F3 * F3];      // round(s_k*W1[k][n])^T, [N][K]
__device__ float g_s[F3];
__device__ float g_t[F3];
__device__ float g_bias[F3];                   // t @ W1
__device__ float g_bnsum[F3];
__device__ float g_bnsq[F3];

// ------------------------------- helpers ------------------------------------
__device__ __forceinline__ float tf32r(float v) {
    uint32_t u;
    asm("cvt.rna.tf32.f32 %0, %1;" : "=r"(u) : "f"(v));
    return __uint_as_float(u);
}
__device__ __forceinline__ float4 tf32r4(float4 v) {
    return make_float4(tf32r(v.x), tf32r(v.y), tf32r(v.z), tf32r(v.w));
}
__device__ __forceinline__ uint32_t smem_u32(const void* p) {
    uint32_t a;
    asm("{ .reg .u64 t; cvta.to.shared.u64 t, %1; cvt.u32.u64 %0, t; }"
        : "=r"(a) : "l"(p));
    return a;
}
__device__ __forceinline__ void cp_async16(uint32_t dst, const void* src) {
    asm volatile("cp.async.cg.shared.global [%0], [%1], 16;" :: "r"(dst), "l"(src));
}
#define CP_COMMIT() asm volatile("cp.async.commit_group;" ::: "memory")
#define CP_WAIT(n)  asm volatile("cp.async.wait_group %0;" :: "n"(n) : "memory")

__device__ __forceinline__ void ldsm4(uint32_t& r0, uint32_t& r1, uint32_t& r2,
                                      uint32_t& r3, uint32_t addr) {
    asm volatile("ldmatrix.sync.aligned.m8n8.x4.shared.b16 {%0,%1,%2,%3}, [%4];"
                 : "=r"(r0), "=r"(r1), "=r"(r2), "=r"(r3) : "r"(addr));
}
__device__ __forceinline__ void mma_tf32(float* c, const uint32_t* a, const uint32_t* b) {
    asm volatile(
        "mma.sync.aligned.m16n8k8.row.col.f32.tf32.tf32.f32 "
        "{%0,%1,%2,%3}, {%4,%5,%6,%7}, {%8,%9}, {%0,%1,%2,%3};"
        : "+f"(c[0]), "+f"(c[1]), "+f"(c[2]), "+f"(c[3])
        : "r"(a[0]), "r"(a[1]), "r"(a[2]), "r"(a[3]), "r"(b[0]), "r"(b[1]));
}

// ---------------------------------------------------------------------------
// Gather + mean-pool over a row range [off, off+count).
// ---------------------------------------------------------------------------
__global__ void gather_kernel(const float* __restrict__ feat,
                              const int*  __restrict__ neigh,
                              float* __restrict__ aggO, int off)
{
    const int m = blockIdx.x + off;
    __shared__ int idx[DEG];
    if (threadIdx.x < DEG) idx[threadIdx.x] = neigh[(size_t)m * DEG + threadIdx.x];
    __syncthreads();

    const int c = threadIdx.x * 4;

    float4 v0 = *(const float4*)(feat + (size_t)idx[0] * FEAT + c);
    float sx = v0.x, sy = v0.y, sz = v0.z, sw = v0.w;
#pragma unroll 8
    for (int j = 1; j < DEG; j++) {
        float4 v = *(const float4*)(feat + (size_t)idx[j] * FEAT + c);
        sx += v.x; sy += v.y; sz += v.z; sw += v.w;
    }
    const float r32 = 1.0f / 32.0f;
    const float r31 = 1.0f / 31.0f;
    float4 agg = make_float4(sx * r32, sy * r32, sz * r32, sw * r32);
    float4 env = make_float4((sx - v0.x) * r31, (sy - v0.y) * r31,
                             (sz - v0.z) * r31, (sw - v0.w) * r31);

    *(float4*)(g_cat + (size_t)m * F2 + c)        = tf32r4(v0);
    *(float4*)(g_cat + (size_t)m * F2 + FEAT + c) = tf32r4(agg);
    *(float4*)(aggO  + (size_t)m * FEAT + c)      = agg;     // exact output
    *(float4*)(g_env + (size_t)m * FEAT + c)      = tf32r4(env);
}

// ---------------------------------------------------------------------------
// Transpose kernels: ROUND=true applies tf32 rounding to the output.
// ---------------------------------------------------------------------------
template <bool ROUND>
__global__ void transpose_k(const float* __restrict__ src,
                            float* __restrict__ dst, int R, int C)
{
    __shared__ float t[32][33];
    const int bx = blockIdx.x * 32, by = blockIdx.y * 32;
#pragma unroll
    for (int j = 0; j < 32; j += 8)
        t[threadIdx.y + j][threadIdx.x] =
            src[(size_t)(by + threadIdx.y + j) * C + bx + threadIdx.x];
    __syncthreads();
#pragma unroll
    for (int j = 0; j < 32; j += 8) {
        float v = t[threadIdx.x][threadIdx.y + j];
        dst[(size_t)(bx + threadIdx.y + j) * R + by + threadIdx.x] =
            ROUND ? tf32r(v) : v;
    }
}

// ---------------------------------------------------------------------------
// W1sT[n][k] = round(s[k] * W1T[n][k]);  bias[n] = sum_k t[k]*W1T[n][k].
// One block per n-row; rows contiguous (K-major). No atomics.
// ---------------------------------------------------------------------------
__global__ void w1_scale_bias(void)
{
    const int n = blockIdx.x;
    const float4* row = (const float4*)(g_W1T + (size_t)n * F3);
    float4* dst = (float4*)(g_W1sT + (size_t)n * F3);
    float part = 0.f;
    for (int k4 = threadIdx.x; k4 < F3 / 4; k4 += blockDim.x) {
        float4 v = row[k4];
        float4 s4 = *(const float4*)(g_s + k4 * 4);
        float4 t4 = *(const float4*)(g_t + k4 * 4);
        dst[k4] = tf32r4(make_float4(v.x * s4.x, v.y * s4.y,
                                     v.z * s4.z, v.w * s4.w));
        part += t4.x * v.x + t4.y * v.y + t4.z * v.z + t4.w * v.w;
    }
    __shared__ float red[256];
    red[threadIdx.x] = part;
    __syncthreads();
    for (int o = 128; o > 0; o >>= 1) {
        if (threadIdx.x < o) red[threadIdx.x] += red[threadIdx.x + o];
        __syncthreads();
    }
    if (threadIdx.x == 0) g_bias[n] = red[0];
}

// ---------------------------------------------------------------------------
// tf32 mma.sync GEMM core (R8 config): block 128x256x32, 256 thr,
// 8 warps (2x4), warp 64x64, 4-stage cp.async ring, ldmatrix loads,
// register-double-buffered fragments, deferred cp.async issue.
// MODE 0: C0=raw, C1=relu. MODE 2: + C2=round(relu) + fused gen BN stats.
// MODE 1: C0=relu(acc+bias).
// ---------------------------------------------------------------------------
#define BM 128
#define BN 256
#define BK 32
#define NSTAGE 4
#define OP_STRIDE 144                              // 36 floats per row
#define A_BYTES (BM * OP_STRIDE)                   // 18432
#define B_BYTES (BN * OP_STRIDE)                   // 36864
#define STAGE_BYTES (A_BYTES + B_BYTES)            // 55296

template <int MODE>
__device__ __forceinline__ void
run_gemm(char* smem,
         const float* __restrict__ A, const float* __restrict__ A2,
         const float* __restrict__ BT,
         float* __restrict__ C0, float* __restrict__ C1, float* __restrict__ C2,
         const float* __restrict__ bias,
         int K, int splitK, int lda, int lda2, int ldb, int ldc,
         int m0, int n0)
{
    const uint32_t sbase = smem_u32(smem);
    const int tid = threadIdx.x, wid = tid >> 5, lane = tid & 31;
    const int wm = wid >> 2, wn = wid & 3;       // warp grid 2 x 4
    const int lr = lane >> 2, lc = lane & 3;
    const int T = K / BK;

    const float* Bp = BT + (size_t)n0 * ldb;

    auto load_stage = [&](int blk, int s) {
        const uint32_t a_s = sbase + (uint32_t)s * STAGE_BYTES;
        const uint32_t b_s = a_s + A_BYTES;
        const int k0 = blk * BK;
        const float* Ap;
        int ld;
        if (k0 < splitK) { Ap = A + (size_t)m0 * lda + k0;             ld = lda;  }
        else             { Ap = A2 + (size_t)m0 * lda2 + (k0 - splitK); ld = lda2; }
#pragma unroll
        for (int u = 0; u < 4; u++) {            // A: 1024 16B chunks
            int ch = tid + u * 256;
            int row = ch >> 3, c16 = ch & 7;
            cp_async16(a_s + (uint32_t)row * OP_STRIDE + c16 * 16,
                       Ap + (size_t)row * ld + c16 * 4);
        }
#pragma unroll
        for (int u = 0; u < 8; u++) {            // B: 2048 16B chunks
            int ch = tid + u * 256;
            int row = ch >> 3, c16 = ch & 7;
            cp_async16(b_s + (uint32_t)row * OP_STRIDE + c16 * 16,
                       Bp + (size_t)row * ldb + k0 + c16 * 4);
        }
    };

    // ldmatrix per-lane base offsets
    const int a_row = wm * 64 + (lane & 15);
    const int a_col = (lane >> 4) * 4;
    const uint32_t aOff = (uint32_t)a_row * OP_STRIDE + a_col * 4;
    const int b_row = wn * 64 + (lane & 7) + (lane >> 4) * 8;
    const int b_col = ((lane >> 3) & 1) * 4;
    const uint32_t bOff = (uint32_t)b_row * OP_STRIDE + b_col * 4;

    auto load_frags = [&](int s, int k8, uint32_t a[4][4], uint32_t b[4][4]) {
        const uint32_t a_s = sbase + (uint32_t)s * STAGE_BYTES + (uint32_t)k8 * 32;
        const uint32_t b_s = a_s + A_BYTES;
#pragma unroll
        for (int mi = 0; mi < 4; mi++)
            ldsm4(a[mi][0], a[mi][1], a[mi][2], a[mi][3],
                  a_s + aOff + (uint32_t)mi * (16 * OP_STRIDE));
#pragma unroll
        for (int nb = 0; nb < 4; nb++)
            ldsm4(b[nb][0], b[nb][1], b[nb][2], b[nb][3],
                  b_s + bOff + (uint32_t)nb * (16 * OP_STRIDE));
    };

    float acc[4][8][4];
#pragma unroll
    for (int i = 0; i < 4; i++)
#pragma unroll
        for (int j = 0; j < 8; j++)
#pragma unroll
            for (int r = 0; r < 4; r++) acc[i][j][r] = 0.f;

    load_stage(0, 0); CP_COMMIT();
    load_stage(1, 1); CP_COMMIT();
    load_stage(2, 2); CP_COMMIT();

    CP_WAIT(2);               // stage 0 complete
    __syncthreads();

    uint32_t a_cur[4][4], b_cur[4][4], a_nxt[4][4], b_nxt[4][4];
    load_frags(0, 0, a_cur, b_cur);

    for (int i = 0; i < T; i++) {
        CP_WAIT(1);
        __syncthreads();      // stages <= i+1 complete & visible

#pragma unroll
        for (int k8 = 0; k8 < BK / 8; k8++) {
            if (k8 < 3)           load_frags(i & 3, k8 + 1, a_nxt, b_nxt);
            else if (i + 1 < T)   load_frags((i + 1) & 3, 0, a_nxt, b_nxt);
#pragma unroll
            for (int mi = 0; mi < 4; mi++)
#pragma unroll
                for (int nb = 0; nb < 4; nb++) {
                    mma_tf32(acc[mi][2 * nb + 0], a_cur[mi], &b_cur[nb][0]);
                    mma_tf32(acc[mi][2 * nb + 1], a_cur[mi], &b_cur[nb][2]);
                }
            if (k8 == 0) {    // issue next stage AFTER first MMA batch
                if (i + 3 < T) load_stage(i + 3, (i + 3) & 3);
                CP_COMMIT();
            }
#pragma unroll
            for (int mi = 0; mi < 4; mi++)
#pragma unroll
                for (int r = 0; r < 4; r++) a_cur[mi][r] = a_nxt[mi][r];
#pragma unroll
            for (int nb = 0; nb < 4; nb++)
#pragma unroll
                for (int r = 0; r < 4; r++) b_cur[nb][r] = b_nxt[nb][r];
        }
    }

    // Epilogue: stores
#pragma unroll
    for (int mi = 0; mi < 4; mi++) {
#pragma unroll
        for (int half = 0; half < 2; half++) {
            const size_t row = (size_t)m0 + wm * 64 + mi * 16 + lr + half * 8;
#pragma unroll
            for (int ni = 0; ni < 8; ni++) {
                const int col = n0 + wn * 64 + ni * 8 + lc * 2;
                float x = acc[mi][ni][half * 2 + 0];
                float y = acc[mi][ni][half * 2 + 1];
                if (MODE == 1) {
                    x = fmaxf(x + bias[col], 0.f);
                    y = fmaxf(y + bias[col + 1], 0.f);
                    *(float2*)(C0 + row * ldc + col) = make_float2(x, y);
                } else {
                    *(float2*)(C0 + row * ldc + col) = make_float2(x, y);
                    float rx = fmaxf(x, 0.f), ry = fmaxf(y, 0.f);
                    *(float2*)(C1 + row * ldc + col) = make_float2(rx, ry);
                    if (MODE == 2)
                        *(float2*)(C2 + row * ldc + col) =
                            make_float2(tf32r(rx), tf32r(ry));
                }
            }
        }
    }

    // Fused BN stats over gen = relu(acc) (MODE 2 only).
    if (MODE == 2) {
#pragma unroll
        for (int ni = 0; ni < 8; ni++) {
            float s0 = 0.f, q0 = 0.f, s1 = 0.f, q1 = 0.f;
#pragma unroll
            for (int mi = 0; mi < 4; mi++) {
#pragma unroll
                for (int half = 0; half < 2; half++) {
                    float rx = fmaxf(acc[mi][ni][half * 2 + 0], 0.f);
                    float ry = fmaxf(acc[mi][ni][half * 2 + 1], 0.f);
                    s0 += rx; q0 += rx * rx;
                    s1 += ry; q1 += ry * ry;
                }
            }
#pragma unroll
            for (int msk = 4; msk <= 16; msk <<= 1) {
                s0 += __shfl_xor_sync(0xffffffffu, s0, msk);
                q0 += __shfl_xor_sync(0xffffffffu, q0, msk);
                s1 += __shfl_xor_sync(0xffffffffu, s1, msk);
                q1 += __shfl_xor_sync(0xffffffffu, q1, msk);
            }
            if (lr == 0) {
                const int col = n0 + wn * 64 + ni * 8 + lc * 2;
                atomicAdd(&g_bnsum[FEAT + col],     s0);
                atomicAdd(&g_bnsq [FEAT + col],     q0);
                atomicAdd(&g_bnsum[FEAT + col + 1], s1);
                atomicAdd(&g_bnsq [FEAT + col + 1], q1);
            }
        }
    }
}

// Merged GEMM1+GEMM2: flat interleaved grid; `boff` selects the bid window
// so batch halves can launch on separate streams.
__global__ void __launch_bounds__(256)
mma_gemm12(const float* __restrict__ cat, const float* __restrict__ env,
           const float* __restrict__ WgT,
           float* __restrict__ raw, float* __restrict__ gen,
           float* __restrict__ genr,
           float* __restrict__ eraw, float* __restrict__ egen, int boff)
{
    extern __shared__ __align__(16) char smem[];
    const int bid = blockIdx.x + boff;
    const int z = bid & 1;
    const int t = bid >> 1;              // 0..255
    const int n0 = (t & 3) * BN;
    const int m0 = (t >> 2) * BM;

    if (z == 0) {
        run_gemm<2>(smem, cat, cat, WgT, raw, gen, genr, nullptr,
                    F2, F2, F2, F2, F2, F2, m0, n0);
    } else {
        run_gemm<0>(smem, env, env, WgT + FEAT, eraw, egen, nullptr, nullptr,
                    FEAT, FEAT, FEAT, FEAT, F2, F2, m0, n0);
    }
}

// GEMM3: to = relu([aggR | genr] @ W1sT + bias), A split at k=FEAT.
__global__ void __launch_bounds__(256)
mma_gemm3(const float* __restrict__ aggR, const float* __restrict__ genr,
          const float* __restrict__ W1sT, float* __restrict__ C0,
          const float* __restrict__ bias)
{
    extern __shared__ __align__(16) char smem[];
    const int m0 = blockIdx.y * BM, n0 = blockIdx.x * BN;
    run_gemm<1>(smem, aggR, genr, W1sT, C0, nullptr, nullptr, bias,
                F3, FEAT, F2, F2, F3, F3, m0, n0);
}

// ---------------------------------------------------------------------------
// BN stats for agg columns only (0..511); gen stats come from GEMM12 epilogue.
// ---------------------------------------------------------------------------
__global__ void bn_stats_agg(const float* __restrict__ agg)
{
    const int c0 = blockIdx.x * 32;
    const int cx = threadIdx.x & 31;
    const int ry = threadIdx.x >> 5;
    const int c  = c0 + cx;

    const float* base = agg + c;

    const int r0 = blockIdx.y * 512;
    float sum = 0.f, sq = 0.f;
#pragma unroll 8
    for (int r = r0 + ry; r < r0 + 512; r += 8) {
        float v = base[(size_t)r * FEAT];
        sum += v; sq += v * v;
    }
    __shared__ float ssum[8][32], ssq[8][32];
    ssum[ry][cx] = sum; ssq[ry][cx] = sq;
    __syncthreads();
    if (ry == 0) {
#pragma unroll
        for (int r = 1; r < 8; r++) { sum += ssum[r][cx]; sq += ssq[r][cx]; }
        atomicAdd(&g_bnsum[c], sum);
        atomicAdd(&g_bnsq[c], sq);
    }
}

__global__ void bn_finalize(const float* __restrict__ gamma,
                            const float* __restrict__ beta)
{
    int c = blockIdx.x * blockDim.x + threadIdx.x;
    if (c >= F3) return;
    const float inv = 1.0f / (float)BATCH;
    float mean = g_bnsum[c] * inv;
    float var  = g_bnsq[c] * inv - mean * mean;
    float s = gamma[c] * rsqrtf(var + BN_EPS);
    g_s[c] = s;
    g_t[c] = beta[c] - mean * s;
}

// ---------------------------------------------------------------------------
extern "C" void kernel_launch(void* const* d_in, const int* in_sizes, int n_in,
                              void* d_out, int out_size)
{
    const float* feat  = (const float*)d_in[0];
    const float* Wg    = (const float*)d_in[1];
    const float* W1    = (const float*)d_in[2];
    const float* gamma = (const float*)d_in[3];
    const float* beta  = (const float*)d_in[4];
    const int*   neigh = (const int*)d_in[6];

    float* out   = (float*)d_out;
    float* aggO  = out + OFF_AGG;
    float* toO   = out + OFF_TO;
    float* genO  = out + OFF_GEN;
    float* rawO  = out + OFF_RAW;
    float* egenO = out + OFF_EGEN;
    float* erawO = out + OFF_ERAW;

    float *p_cat, *p_env, *p_genr, *p_WgT, *p_W1T, *p_W1sT, *p_sum, *p_sq, *p_bias;
    cudaGetSymbolAddress((void**)&p_cat,  g_cat);
    cudaGetSymbolAddress((void**)&p_env,  g_env);
    cudaGetSymbolAddress((void**)&p_genr, g_genr);
    cudaGetSymbolAddress((void**)&p_WgT,  g_WgT);
    cudaGetSymbolAddress((void**)&p_W1T,  g_W1T);
    cudaGetSymbolAddress((void**)&p_W1sT, g_W1sT);
    cudaGetSymbolAddress((void**)&p_sum,  g_bnsum);
    cudaGetSymbolAddress((void**)&p_sq,   g_bnsq);
    cudaGetSymbolAddress((void**)&p_bias, g_bias);

    const int smem_bytes = NSTAGE * STAGE_BYTES;   // 221184
    cudaFuncSetAttribute(mma_gemm12, cudaFuncAttributeMaxDynamicSharedMemorySize, smem_bytes);
    cudaFuncSetAttribute(mma_gemm3,  cudaFuncAttributeMaxDynamicSharedMemorySize, smem_bytes);

    cudaStream_t s2;
    cudaStreamCreateWithFlags(&s2, cudaStreamNonBlocking);
    cudaEvent_t eFork, eW, eG1, eS2;
    cudaEventCreateWithFlags(&eFork, cudaEventDisableTiming);
    cudaEventCreateWithFlags(&eW,    cudaEventDisableTiming);
    cudaEventCreateWithFlags(&eG1,   cudaEventDisableTiming);
    cudaEventCreateWithFlags(&eS2,   cudaEventDisableTiming);

    // Fork s2 off the (capturing) default stream.
    cudaEventRecord(eFork, 0);
    cudaStreamWaitEvent(s2, eFork, 0);

    // s2 branch: weight prep + stat memsets (independent of gather).
    transpose_k<true ><<<dim3(F2/32, F2/32), dim3(32, 8), 0, s2>>>(Wg, p_WgT, F2, F2);
    transpose_k<false><<<dim3(F3/32, F3/32), dim3(32, 8), 0, s2>>>(W1, p_W1T, F3, F3);
    cudaMemsetAsync(p_sum, 0, F3 * sizeof(float), s2);
    cudaMemsetAsync(p_sq,  0, F3 * sizeof(float), s2);
    cudaEventRecord(eW, s2);

    // Main stream: gather first half (rows 0..4095).
    gather_kernel<<<BATCH / 2, 128>>>(feat, neigh, aggO, 0);
    cudaEventRecord(eG1, 0);

    // Main: GEMM12 half A (m0 < 4096; needs WgT + memsets).
    cudaStreamWaitEvent(0, eW, 0);
    mma_gemm12<<<256, 256, smem_bytes>>>(
        p_cat, p_env, p_WgT, rawO, genO, p_genr, erawO, egenO, 0);

    // s2: gather second half (overlaps GEMM12-A), then GEMM12 half B,
    //     then agg BN stats.
    cudaStreamWaitEvent(s2, eG1, 0);
    gather_kernel<<<BATCH / 2, 128, 0, s2>>>(feat, neigh, aggO, BATCH / 2);
    mma_gemm12<<<256, 256, smem_bytes, s2>>>(
        p_cat, p_env, p_WgT, rawO, genO, p_genr, erawO, egenO, 256);
    bn_stats_agg<<<dim3(FEAT/32, 16), 256, 0, s2>>>(aggO);
    cudaEventRecord(eS2, s2);

    // Main: join; finalize BN, build scaled W1 + bias, GEMM3.
    cudaStreamWaitEvent(0, eS2, 0);
    bn_finalize<<<F3/256, 256>>>(gamma, beta);
    w1_scale_bias<<<F3, 256>>>();
    mma_gemm3<<<dim3(F3/BN, BATCH/BM), 256, smem_bytes>>>(
        p_cat + FEAT, p_genr, p_W1sT, toO, p_bias);

    (void)in_sizes; (void)n_in; (void)out_size;
}

// round 17
// speedup vs baseline: 1.5086x; 1.5086x over previous
#include <cuda_runtime.h>
#include <cuda_fp16.h>
#include <cstdint>

// Problem constants
#define BATCH 8192
#define FEAT  512
#define DEG   32
#define F2    1024   // 2*FEAT
#define F3    1536   // 3*FEAT
#define BN_EPS 1e-5f

// Output layout (floats): agg, to_feats, gen, raw, env_gen, env_raw
#define OFF_AGG   0
#define OFF_TO    (BATCH*FEAT)
#define OFF_GEN   (OFF_TO   + BATCH*F3)
#define OFF_RAW   (OFF_GEN  + BATCH*F2)
#define OFF_EGEN  (OFF_RAW  + BATCH*F2)
#define OFF_ERAW  (OFF_EGEN + BATCH*F2)

// ---------------- scratch (__device__ globals; no allocations) --------------
__device__ __half g_cat [(size_t)BATCH * F2];   // [self | agg] fp16
__device__ __half g_env [(size_t)BATCH * FEAT]; // env_agg fp16
__device__ __half g_genr[(size_t)BATCH * F2];   // fp16 relu(raw) = gen
__device__ __half g_WgT [(size_t)F2 * F2];      // W_gen^T fp16, [N][K] K-major
__device__ float  g_W1T [(size_t)F3 * F3];      // W1^T exact fp32, [N][K]
__device__ __half g_W1sT[(size_t)F3 * F3];      // fp16(s_k*W1[k][n])^T, [N][K]
__device__ float g_s[F3];
__device__ float g_t[F3];
__device__ float g_bias[F3];                    // t @ W1
__device__ float g_bnsum[F3];
__device__ float g_bnsq[F3];

// ------------------------------- helpers ------------------------------------
__device__ __forceinline__ uint32_t smem_u32(const void* p) {
    uint32_t a;
    asm("{ .reg .u64 t; cvta.to.shared.u64 t, %1; cvt.u32.u64 %0, t; }"
        : "=r"(a) : "l"(p));
    return a;
}
__device__ __forceinline__ void cp_async16(uint32_t dst, const void* src) {
    asm volatile("cp.async.cg.shared.global [%0], [%1], 16;" :: "r"(dst), "l"(src));
}
#define CP_COMMIT() asm volatile("cp.async.commit_group;" ::: "memory")
#define CP_WAIT(n)  asm volatile("cp.async.wait_group %0;" :: "n"(n) : "memory")

__device__ __forceinline__ void ldsm4(uint32_t& r0, uint32_t& r1, uint32_t& r2,
                                      uint32_t& r3, uint32_t addr) {
    asm volatile("ldmatrix.sync.aligned.m8n8.x4.shared.b16 {%0,%1,%2,%3}, [%4];"
                 : "=r"(r0), "=r"(r1), "=r"(r2), "=r"(r3) : "r"(addr));
}
// fp16 MMA: D(f32) = A(f16) * B(f16) + D;  m16n8k16.
__device__ __forceinline__ void mma_f16(float* c, const uint32_t* a, const uint32_t* b) {
    asm volatile(
        "mma.sync.aligned.m16n8k16.row.col.f32.f16.f16.f32 "
        "{%0,%1,%2,%3}, {%4,%5,%6,%7}, {%8,%9}, {%0,%1,%2,%3};"
        : "+f"(c[0]), "+f"(c[1]), "+f"(c[2]), "+f"(c[3])
        : "r"(a[0]), "r"(a[1]), "r"(a[2]), "r"(a[3]), "r"(b[0]), "r"(b[1]));
}

// ---------------------------------------------------------------------------
// Gather + mean-pool (fp16 staging for GEMMs; exact fp32 agg output).
// ---------------------------------------------------------------------------
__global__ void gather_kernel(const float* __restrict__ feat,
                              const int*  __restrict__ neigh,
                              float* __restrict__ aggO)
{
    const int m = blockIdx.x;
    __shared__ int idx[DEG];
    if (threadIdx.x < DEG) idx[threadIdx.x] = neigh[(size_t)m * DEG + threadIdx.x];
    __syncthreads();

    const int c = threadIdx.x * 4;

    float4 v0 = *(const float4*)(feat + (size_t)idx[0] * FEAT + c);
    float sx = v0.x, sy = v0.y, sz = v0.z, sw = v0.w;
#pragma unroll 8
    for (int j = 1; j < DEG; j++) {
        float4 v = *(const float4*)(feat + (size_t)idx[j] * FEAT + c);
        sx += v.x; sy += v.y; sz += v.z; sw += v.w;
    }
    const float r32 = 1.0f / 32.0f;
    const float r31 = 1.0f / 31.0f;
    float4 agg = make_float4(sx * r32, sy * r32, sz * r32, sw * r32);
    float4 env = make_float4((sx - v0.x) * r31, (sy - v0.y) * r31,
                             (sz - v0.z) * r31, (sw - v0.w) * r31);

    __half2* pc = (__half2*)(g_cat + (size_t)m * F2 + c);
    pc[0] = __floats2half2_rn(v0.x, v0.y);
    pc[1] = __floats2half2_rn(v0.z, v0.w);
    __half2* pa = (__half2*)(g_cat + (size_t)m * F2 + FEAT + c);
    pa[0] = __floats2half2_rn(agg.x, agg.y);
    pa[1] = __floats2half2_rn(agg.z, agg.w);
    *(float4*)(aggO + (size_t)m * FEAT + c) = agg;     // exact output
    __half2* pe = (__half2*)(g_env + (size_t)m * FEAT + c);
    pe[0] = __floats2half2_rn(env.x, env.y);
    pe[1] = __floats2half2_rn(env.z, env.w);
}

// ---------------------------------------------------------------------------
// Transposes: fp16 output (weights for MMA) and fp32 output (exact W1^T).
// ---------------------------------------------------------------------------
__global__ void transpose_h(const float* __restrict__ src,
                            __half* __restrict__ dst, int R, int C)
{
    __shared__ float t[32][33];
    const int bx = blockIdx.x * 32, by = blockIdx.y * 32;
#pragma unroll
    for (int j = 0; j < 32; j += 8)
        t[threadIdx.y + j][threadIdx.x] =
            src[(size_t)(by + threadIdx.y + j) * C + bx + threadIdx.x];
    __syncthreads();
#pragma unroll
    for (int j = 0; j < 32; j += 8)
        dst[(size_t)(bx + threadIdx.y + j) * R + by + threadIdx.x] =
            __float2half_rn(t[threadIdx.x][threadIdx.y + j]);
}

__global__ void transpose_f(const float* __restrict__ src,
                            float* __restrict__ dst, int R, int C)
{
    __shared__ float t[32][33];
    const int bx = blockIdx.x * 32, by = blockIdx.y * 32;
#pragma unroll
    for (int j = 0; j < 32; j += 8)
        t[threadIdx.y + j][threadIdx.x] =
            src[(size_t)(by + threadIdx.y + j) * C + bx + threadIdx.x];
    __syncthreads();
#pragma unroll
    for (int j = 0; j < 32; j += 8)
        dst[(size_t)(bx + threadIdx.y + j) * R + by + threadIdx.x] =
            t[threadIdx.x][threadIdx.y + j];
}

// ---------------------------------------------------------------------------
// W1sT[n][k] = fp16(s[k] * W1T[n][k]);  bias[n] = sum_k t[k]*W1T[n][k].
// One block per n-row; rows contiguous (K-major). No atomics.
// ---------------------------------------------------------------------------
__global__ void w1_scale_bias(void)
{
    const int n = blockIdx.x;
    const float4* row = (const float4*)(g_W1T + (size_t)n * F3);
    __half2* dst = (__half2*)(g_W1sT + (size_t)n * F3);
    float part = 0.f;
    for (int k4 = threadIdx.x; k4 < F3 / 4; k4 += blockDim.x) {
        float4 v = row[k4];
        float4 s4 = *(const float4*)(g_s + k4 * 4);
        float4 t4 = *(const float4*)(g_t + k4 * 4);
        dst[k4 * 2 + 0] = __floats2half2_rn(v.x * s4.x, v.y * s4.y);
        dst[k4 * 2 + 1] = __floats2half2_rn(v.z * s4.z, v.w * s4.w);
        part += t4.x * v.x + t4.y * v.y + t4.z * v.z + t4.w * v.w;
    }
    __shared__ float red[256];
    red[threadIdx.x] = part;
    __syncthreads();
    for (int o = 128; o > 0; o >>= 1) {
        if (threadIdx.x < o) red[threadIdx.x] += red[threadIdx.x + o];
        __syncthreads();
    }
    if (threadIdx.x == 0) g_bias[n] = red[0];
}

// ---------------------------------------------------------------------------
// fp16 mma.sync GEMM core: block 128x256x32, 256 thr, 8 warps (2x4),
// warp 64x64, 4-stage cp.async ring, ldmatrix.x4 b16 loads,
// register-double-buffered fragments, deferred cp.async issue.
// Per k-block: 2 k16 steps, 64 MMAs (m16n8k16).
// MODE 0: C0=raw, C1=relu. MODE 2: + C2=fp16(relu) + fused gen BN stats.
// MODE 1: C0=relu(acc+bias).
// SMEM rows: 32 halves = 64 B data, padded to 80 B (LDSM conflict-free).
// ---------------------------------------------------------------------------
#define BM 128
#define BN 256
#define BK 32
#define NSTAGE 4
#define OPS 80                                     // row stride bytes
#define A_BYTES (BM * OPS)                         // 10240
#define B_BYTES (BN * OPS)                         // 20480
#define STAGE_BYTES (A_BYTES + B_BYTES)            // 30720

template <int MODE>
__device__ __forceinline__ void
run_gemm(char* smem,
         const __half* __restrict__ A, const __half* __restrict__ A2,
         const __half* __restrict__ BT,
         float* __restrict__ C0, float* __restrict__ C1,
         __half* __restrict__ C2,
         const float* __restrict__ bias,
         int K, int splitK, int lda, int lda2, int ldb, int ldc,
         int m0, int n0)
{
    const uint32_t sbase = smem_u32(smem);
    const int tid = threadIdx.x, wid = tid >> 5, lane = tid & 31;
    const int wm = wid >> 2, wn = wid & 3;       // warp grid 2 x 4
    const int lr = lane >> 2, lc = lane & 3;
    const int T = K / BK;

    const __half* Bp = BT + (size_t)n0 * ldb;

    auto load_stage = [&](int blk, int s) {
        const uint32_t a_s = sbase + (uint32_t)s * STAGE_BYTES;
        const uint32_t b_s = a_s + A_BYTES;
        const int k0 = blk * BK;
        const __half* Ap;
        int ld;
        if (k0 < splitK) { Ap = A + (size_t)m0 * lda + k0;              ld = lda;  }
        else             { Ap = A2 + (size_t)m0 * lda2 + (k0 - splitK); ld = lda2; }
#pragma unroll
        for (int u = 0; u < 2; u++) {            // A: 512 16B chunks
            int ch = tid + u * 256;
            int row = ch >> 2, c16 = ch & 3;
            cp_async16(a_s + (uint32_t)row * OPS + c16 * 16,
                       Ap + (size_t)row * ld + c16 * 8);
        }
#pragma unroll
        for (int u = 0; u < 4; u++) {            // B: 1024 16B chunks
            int ch = tid + u * 256;
            int row = ch >> 2, c16 = ch & 3;
            cp_async16(b_s + (uint32_t)row * OPS + c16 * 16,
                       Bp + (size_t)row * ldb + k0 + c16 * 8);
        }
    };

    // ldmatrix per-lane base offsets (b16, k16 steps)
    //  A m16k16: lanes 0-15 -> rows, lanes 16-31 -> +16B (k8-15)
    const int a_row = wm * 64 + (lane & 15);
    const uint32_t aOff = (uint32_t)a_row * OPS + (lane >> 4) * 16;
    //  B (two n8 blocks x k16): lanes 0-7 n0-7/k0, 8-15 n0-7/k8,
    //                           16-23 n8-15/k0, 24-31 n8-15/k8
    const int b_row = wn * 64 + (lane & 7) + ((lane >> 4) * 8);
    const uint32_t bOff = (uint32_t)b_row * OPS + ((lane >> 3) & 1) * 16;

    auto load_frags = [&](int s, int ks, uint32_t a[4][4], uint32_t b[4][4]) {
        const uint32_t a_s = sbase + (uint32_t)s * STAGE_BYTES + (uint32_t)ks * 32;
        const uint32_t b_s = a_s + A_BYTES;
#pragma unroll
        for (int mi = 0; mi < 4; mi++)
            ldsm4(a[mi][0], a[mi][1], a[mi][2], a[mi][3],
                  a_s + aOff + (uint32_t)mi * (16 * OPS));
#pragma unroll
        for (int nb = 0; nb < 4; nb++)
            ldsm4(b[nb][0], b[nb][1], b[nb][2], b[nb][3],
                  b_s + bOff + (uint32_t)nb * (16 * OPS));
    };

    float acc[4][8][4];
#pragma unroll
    for (int i = 0; i < 4; i++)
#pragma unroll
        for (int j = 0; j < 8; j++)
#pragma unroll
            for (int r = 0; r < 4; r++) acc[i][j][r] = 0.f;

    load_stage(0, 0); CP_COMMIT();
    load_stage(1, 1); CP_COMMIT();
    load_stage(2, 2); CP_COMMIT();

    CP_WAIT(2);               // stage 0 complete
    __syncthreads();

    uint32_t a_cur[4][4], b_cur[4][4], a_nxt[4][4], b_nxt[4][4];
    load_frags(0, 0, a_cur, b_cur);

    for (int i = 0; i < T; i++) {
        CP_WAIT(1);
        __syncthreads();      // stages <= i+1 complete & visible

#pragma unroll
        for (int ks = 0; ks < 2; ks++) {         // two k16 steps per k-block
            if (ks == 0)          load_frags(i & 3, 1, a_nxt, b_nxt);
            else if (i + 1 < T)   load_frags((i + 1) & 3, 0, a_nxt, b_nxt);
#pragma unroll
            for (int mi = 0; mi < 4; mi++)
#pragma unroll
                for (int nb = 0; nb < 4; nb++) {
                    mma_f16(acc[mi][2 * nb + 0], a_cur[mi], &b_cur[nb][0]);
                    mma_f16(acc[mi][2 * nb + 1], a_cur[mi], &b_cur[nb][2]);
                }
            if (ks == 0) {    // issue next stage AFTER first MMA batch
                if (i + 3 < T) load_stage(i + 3, (i + 3) & 3);
                CP_COMMIT();
            }
#pragma unroll
            for (int mi = 0; mi < 4; mi++)
#pragma unroll
                for (int r = 0; r < 4; r++) a_cur[mi][r] = a_nxt[mi][r];
#pragma unroll
            for (int nb = 0; nb < 4; nb++)
#pragma unroll
                for (int r = 0; r < 4; r++) b_cur[nb][r] = b_nxt[nb][r];
        }
    }

    // Epilogue: stores
#pragma unroll
    for (int mi = 0; mi < 4; mi++) {
#pragma unroll
        for (int half = 0; half < 2; half++) {
            const size_t row = (size_t)m0 + wm * 64 + mi * 16 + lr + half * 8;
#pragma unroll
            for (int ni = 0; ni < 8; ni++) {
                const int col = n0 + wn * 64 + ni * 8 + lc * 2;
                float x = acc[mi][ni][half * 2 + 0];
                float y = acc[mi][ni][half * 2 + 1];
                if (MODE == 1) {
                    x = fmaxf(x + bias[col], 0.f);
                    y = fmaxf(y + bias[col + 1], 0.f);
                    *(float2*)(C0 + row * ldc + col) = make_float2(x, y);
                } else {
                    *(float2*)(C0 + row * ldc + col) = make_float2(x, y);
                    float rx = fmaxf(x, 0.f), ry = fmaxf(y, 0.f);
                    *(float2*)(C1 + row * ldc + col) = make_float2(rx, ry);
                    if (MODE == 2)
                        *(__half2*)(C2 + row * ldc + col) =
                            __floats2half2_rn(rx, ry);
                }
            }
        }
    }

    // Fused BN stats over gen = relu(acc) (MODE 2 only).
    if (MODE == 2) {
#pragma unroll
        for (int ni = 0; ni < 8; ni++) {
            float s0 = 0.f, q0 = 0.f, s1 = 0.f, q1 = 0.f;
#pragma unroll
            for (int mi = 0; mi < 4; mi++) {
#pragma unroll
                for (int half = 0; half < 2; half++) {
                    float rx = fmaxf(acc[mi][ni][half * 2 + 0], 0.f);
                    float ry = fmaxf(acc[mi][ni][half * 2 + 1], 0.f);
                    s0 += rx; q0 += rx * rx;
                    s1 += ry; q1 += ry * ry;
                }
            }
#pragma unroll
            for (int msk = 4; msk <= 16; msk <<= 1) {
                s0 += __shfl_xor_sync(0xffffffffu, s0, msk);
                q0 += __shfl_xor_sync(0xffffffffu, q0, msk);
                s1 += __shfl_xor_sync(0xffffffffu, s1, msk);
                q1 += __shfl_xor_sync(0xffffffffu, q1, msk);
            }
            if (lr == 0) {
                const int col = n0 + wn * 64 + ni * 8 + lc * 2;
                atomicAdd(&g_bnsum[FEAT + col],     s0);
                atomicAdd(&g_bnsq [FEAT + col],     q0);
                atomicAdd(&g_bnsum[FEAT + col + 1], s1);
                atomicAdd(&g_bnsq [FEAT + col + 1], q1);
            }
        }
    }
}

// Merged GEMM1+GEMM2: flat grid of 512, interleaved.
__global__ void __launch_bounds__(256)
mma_gemm12(float* __restrict__ raw, float* __restrict__ gen,
           float* __restrict__ eraw, float* __restrict__ egen)
{
    extern __shared__ __align__(16) char smem[];
    const int bid = blockIdx.x;
    const int z = bid & 1;
    const int t = bid >> 1;              // 0..255
    const int n0 = (t & 3) * BN;
    const int m0 = (t >> 2) * BM;

    if (z == 0) {
        run_gemm<2>(smem, g_cat, g_cat, g_WgT, raw, gen, g_genr, nullptr,
                    F2, F2, F2, F2, F2, F2, m0, n0);
    } else {
        run_gemm<0>(smem, g_env, g_env, g_WgT + FEAT, eraw, egen, nullptr,
                    nullptr, FEAT, FEAT, FEAT, FEAT, F2, F2, m0, n0);
    }
}

// GEMM3: to = relu([aggH | genr] @ W1sT + bias), A split at k=FEAT.
__global__ void __launch_bounds__(256)
mma_gemm3(float* __restrict__ C0, const float* __restrict__ bias)
{
    extern __shared__ __align__(16) char smem[];
    const int m0 = blockIdx.y * BM, n0 = blockIdx.x * BN;
    run_gemm<1>(smem, g_cat + FEAT, g_genr, g_W1sT, C0, nullptr, nullptr, bias,
                F3, FEAT, F2, F2, F3, F3, m0, n0);
}

// ---------------------------------------------------------------------------
// BN stats for agg columns only (0..511); gen stats come from GEMM12 epilogue.
// ---------------------------------------------------------------------------
__global__ void bn_stats_agg(const float* __restrict__ agg)
{
    const int c0 = blockIdx.x * 32;
    const int cx = threadIdx.x & 31;
    const int ry = threadIdx.x >> 5;
    const int c  = c0 + cx;

    const float* base = agg + c;

    const int r0 = blockIdx.y * 512;
    float sum = 0.f, sq = 0.f;
#pragma unroll 8
    for (int r = r0 + ry; r < r0 + 512; r += 8) {
        float v = base[(size_t)r * FEAT];
        sum += v; sq += v * v;
    }
    __shared__ float ssum[8][32], ssq[8][32];
    ssum[ry][cx] = sum; ssq[ry][cx] = sq;
    __syncthreads();
    if (ry == 0) {
#pragma unroll
        for (int r = 1; r < 8; r++) { sum += ssum[r][cx]; sq += ssq[r][cx]; }
        atomicAdd(&g_bnsum[c], sum);
        atomicAdd(&g_bnsq[c], sq);
    }
}

__global__ void bn_finalize(const float* __restrict__ gamma,
                            const float* __restrict__ beta)
{
    int c = blockIdx.x * blockDim.x + threadIdx.x;
    if (c >= F3) return;
    const float inv = 1.0f / (float)BATCH;
    float mean = g_bnsum[c] * inv;
    float var  = g_bnsq[c] * inv - mean * mean;
    float s = gamma[c] * rsqrtf(var + BN_EPS);
    g_s[c] = s;
    g_t[c] = beta[c] - mean * s;
}

// ---------------------------------------------------------------------------
extern "C" void kernel_launch(void* const* d_in, const int* in_sizes, int n_in,
                              void* d_out, int out_size)
{
    const float* feat  = (const float*)d_in[0];
    const float* Wg    = (const float*)d_in[1];
    const float* W1    = (const float*)d_in[2];
    const float* gamma = (const float*)d_in[3];
    const float* beta  = (const float*)d_in[4];
    const int*   neigh = (const int*)d_in[6];

    float* out   = (float*)d_out;
    float* aggO  = out + OFF_AGG;
    float* toO   = out + OFF_TO;
    float* genO  = out + OFF_GEN;
    float* rawO  = out + OFF_RAW;
    float* egenO = out + OFF_EGEN;
    float* erawO = out + OFF_ERAW;

    __half *p_WgT;
    float *p_W1T, *p_sum, *p_sq, *p_bias;
    cudaGetSymbolAddress((void**)&p_WgT,  g_WgT);
    cudaGetSymbolAddress((void**)&p_W1T,  g_W1T);
    cudaGetSymbolAddress((void**)&p_sum,  g_bnsum);
    cudaGetSymbolAddress((void**)&p_sq,   g_bnsq);
    cudaGetSymbolAddress((void**)&p_bias, g_bias);

    const int smem_bytes = NSTAGE * STAGE_BYTES;   // 122880
    cudaFuncSetAttribute(mma_gemm12, cudaFuncAttributeMaxDynamicSharedMemorySize, smem_bytes);
    cudaFuncSetAttribute(mma_gemm3,  cudaFuncAttributeMaxDynamicSharedMemorySize, smem_bytes);

    cudaStream_t s2;
    cudaStreamCreateWithFlags(&s2, cudaStreamNonBlocking);
    cudaEvent_t eFork, eW, eG, eS;
    cudaEventCreateWithFlags(&eFork, cudaEventDisableTiming);
    cudaEventCreateWithFlags(&eW,    cudaEventDisableTiming);
    cudaEventCreateWithFlags(&eG,    cudaEventDisableTiming);
    cudaEventCreateWithFlags(&eS,    cudaEventDisableTiming);

    // Fork s2 off the (capturing) default stream.
    cudaEventRecord(eFork, 0);
    cudaStreamWaitEvent(s2, eFork, 0);

    // s2 branch: weight prep + stat memsets (independent of gather).
    transpose_h<<<dim3(F2/32, F2/32), dim3(32, 8), 0, s2>>>(Wg, p_WgT, F2, F2);
    transpose_f<<<dim3(F3/32, F3/32), dim3(32, 8), 0, s2>>>(W1, p_W1T, F3, F3);
    cudaMemsetAsync(p_sum, 0, F3 * sizeof(float), s2);
    cudaMemsetAsync(p_sq,  0, F3 * sizeof(float), s2);
    cudaEventRecord(eW, s2);

    // Main stream: gather.
    gather_kernel<<<BATCH, 128>>>(feat, neigh, aggO);
    cudaEventRecord(eG, 0);

    // s2: agg BN stats (needs gather + memsets) — overlaps GEMM12.
    cudaStreamWaitEvent(s2, eG, 0);
    bn_stats_agg<<<dim3(FEAT/32, 16), 256, 0, s2>>>(aggO);
    cudaEventRecord(eS, s2);

    // Main: GEMM1+GEMM2 (needs WgT + memsets from s2).
    cudaStreamWaitEvent(0, eW, 0);
    mma_gemm12<<<512, 256, smem_bytes>>>(rawO, genO, erawO, egenO);

    // Join stats branch; finalize BN, build scaled W1 + bias, GEMM3.
    cudaStreamWaitEvent(0, eS, 0);
    bn_finalize<<<F3/256, 256>>>(gamma, beta);
    w1_scale_bias<<<F3, 256>>>();
    mma_gemm3<<<dim3(F3/BN, BATCH/BM), 256, smem_bytes>>>(toO, p_bias);

    (void)in_sizes; (void)n_in; (void)out_size;
}